// round 6
// baseline (speedup 1.0000x reference)
#include <cuda_runtime.h>

// SimpleQNN collapses analytically:
//   z[b,v]  = cos(rx[v]) * sin(x[b,v] - ry[v])        (per-wire <Z> after the 4 1q layers)
//   diagonal layers (CRZ, CZ, RZ) are pure phases -> no effect on probabilities
//   CNOT cascade (Heisenberg picture) -> parity masks:
//       q_0 = prod_{v=1..15} z_v,   q_w = prod_{v=0..w} z_v  (w>=1)
//   out[b,k] = sum_w q[b,w] * W[k,w] + bias[k]
//
// Inputs (metadata order): x(64,16), ry(16), rx(16), rz(16, unused), crz(16, unused),
//                          W(10,16), b(10). Output: float32 (64,10).

#define NW 16
#define BATCH 64
#define NOUT 10

__global__ __launch_bounds__(BATCH, 1)
void simpleqnn_kernel(const float* __restrict__ x,
                      const float* __restrict__ ry,
                      const float* __restrict__ rx,
                      const float* __restrict__ W,
                      const float* __restrict__ bias,
                      float* __restrict__ out) {
    const int b = threadIdx.x;   // blockDim.x == BATCH exactly

    // Vectorized row load: 4 x float4 = 16 floats of x for this batch element.
    float xv[NW];
    const float4* xrow = reinterpret_cast<const float4*>(x + b * NW);
#pragma unroll
    for (int i = 0; i < NW / 4; i++) {
        float4 v = xrow[i];
        xv[4 * i + 0] = v.x; xv[4 * i + 1] = v.y;
        xv[4 * i + 2] = v.z; xv[4 * i + 3] = v.w;
    }

    // Per-wire Z expectation after RY(x), H, RY(ry), RX(rx) on |0>
    float z[NW];
#pragma unroll
    for (int v = 0; v < NW; v++) {
        z[v] = cosf(rx[v]) * sinf(xv[v] - ry[v]);
    }

    // Parity-mask expectations from the CNOT cascade
    float q[NW];
    float p = z[0];
#pragma unroll
    for (int w = 1; w < NW; w++) {
        p *= z[w];
        q[w] = p;
    }
    float s = z[1];
#pragma unroll
    for (int v = 2; v < NW; v++) s *= z[v];
    q[0] = s;

    // Final linear layer: out[b,k] = sum_w q[w] * W[k,w] + bias[k]
#pragma unroll
    for (int k = 0; k < NOUT; k++) {
        float acc = bias[k];
#pragma unroll
        for (int w = 0; w < NW; w++) {
            acc = fmaf(q[w], W[k * NW + w], acc);
        }
        out[b * NOUT + k] = acc;
    }
}

extern "C" void kernel_launch(void* const* d_in, const int* in_sizes, int n_in,
                              void* d_out, int out_size) {
    const float* x    = (const float*)d_in[0];   // (64,16)
    const float* ry   = (const float*)d_in[1];   // (16)
    const float* rx   = (const float*)d_in[2];   // (16)
    // d_in[3] = rz_params (unused: diagonal phases vanish in |psi|^2)
    // d_in[4] = crz_params (unused: same reason)
    const float* W    = (const float*)d_in[5];   // (10,16)
    const float* bias = (const float*)d_in[6];   // (10)
    float* out = (float*)d_out;                  // (64,10)

    simpleqnn_kernel<<<1, BATCH>>>(x, ry, rx, W, bias, out);
}

// round 7
// speedup vs baseline: 1.3478x; 1.3478x over previous
#include <cuda_runtime.h>

// SimpleQNN collapses analytically:
//   z[b,v]  = cos(rx[v]) * sin(x[b,v] - ry[v])        (per-wire <Z> after the 4 1q layers)
//   diagonal layers (CRZ, CZ, RZ) are pure phases -> no effect on probabilities
//   CNOT cascade (Heisenberg picture) -> parity masks:
//       q_0 = prod_{v=1..15} z_v,   q_w = prod_{v=0..w} z_v  (w>=1)
//   out[b,k] = sum_w q[b,w] * W[k,w] + bias[k]
//
// R6 lesson: libm sinf/cosf (full Payne-Hanek path) was the entire kernel cost
// (regs=201, 7.9us latency chain). Inputs are N(0,1)-scale -> MUFU intrinsics
// __sinf/__cosf are accurate to ~1e-6 here; worst-case accumulated error through
// the 16-term prefix product ~2e-5, far under the 1e-3 threshold.
//
// Inputs (metadata order): x(64,16), ry(16), rx(16), rz(16, unused), crz(16, unused),
//                          W(10,16), b(10). Output: float32 (64,10).

#define NW 16
#define BATCH 64
#define NOUT 10

__global__ __launch_bounds__(BATCH, 1)
void simpleqnn_kernel(const float* __restrict__ x,
                      const float* __restrict__ ry,
                      const float* __restrict__ rx,
                      const float* __restrict__ W,
                      const float* __restrict__ bias,
                      float* __restrict__ out) {
    const int b = threadIdx.x;   // blockDim.x == BATCH exactly

    // Vectorized row load: 4 x float4 = 16 floats of x for this batch element.
    float xv[NW];
    const float4* xrow = reinterpret_cast<const float4*>(x + b * NW);
#pragma unroll
    for (int i = 0; i < NW / 4; i++) {
        float4 v = xrow[i];
        xv[4 * i + 0] = v.x; xv[4 * i + 1] = v.y;
        xv[4 * i + 2] = v.z; xv[4 * i + 3] = v.w;
    }

    // Per-wire Z expectation after RY(x), H, RY(ry), RX(rx) on |0>.
    // MUFU fast intrinsics: args are O(1), well inside the fast-reduction range.
    float z[NW];
#pragma unroll
    for (int v = 0; v < NW; v++) {
        z[v] = __cosf(rx[v]) * __sinf(xv[v] - ry[v]);
    }

    // Parity-mask expectations from the CNOT cascade
    float q[NW];
    float p = z[0];
#pragma unroll
    for (int w = 1; w < NW; w++) {
        p *= z[w];
        q[w] = p;
    }
    float s = z[1];
#pragma unroll
    for (int v = 2; v < NW; v++) s *= z[v];
    q[0] = s;

    // Final linear layer: out[b,k] = sum_w q[w] * W[k,w] + bias[k]
#pragma unroll
    for (int k = 0; k < NOUT; k++) {
        float acc = bias[k];
#pragma unroll
        for (int w = 0; w < NW; w++) {
            acc = fmaf(q[w], W[k * NW + w], acc);
        }
        out[b * NOUT + k] = acc;
    }
}

extern "C" void kernel_launch(void* const* d_in, const int* in_sizes, int n_in,
                              void* d_out, int out_size) {
    const float* x    = (const float*)d_in[0];   // (64,16)
    const float* ry   = (const float*)d_in[1];   // (16)
    const float* rx   = (const float*)d_in[2];   // (16)
    // d_in[3] = rz_params (unused: diagonal phases vanish in |psi|^2)
    // d_in[4] = crz_params (unused: same reason)
    const float* W    = (const float*)d_in[5];   // (10,16)
    const float* bias = (const float*)d_in[6];   // (10)
    float* out = (float*)d_out;                  // (64,10)

    simpleqnn_kernel<<<1, BATCH>>>(x, ry, rx, W, bias, out);
}

// round 8
// speedup vs baseline: 1.4162x; 1.0508x over previous
#include <cuda_runtime.h>

// SimpleQNN collapses analytically:
//   z[b,v]  = cos(rx[v]) * sin(x[b,v] - ry[v])        (per-wire <Z> after the 4 1q layers)
//   diagonal layers (CRZ, CZ, RZ) are pure phases -> no effect on probabilities
//   CNOT cascade (Heisenberg picture) -> parity masks:
//       q_0 = prod_{v=1..15} z_v,   q_w = prod_{v=0..w} z_v  (w>=1)
//   out[b,k] = sum_w q[b,w] * W[k,w] + bias[k]
//
// R6: libm sinf/cosf was the kernel (7.9us, regs=201) -> MUFU intrinsics.
// R7: remaining 5.2us is LDG issue + scoreboard on ~212 scalar loads/thread
//     (regs=216 from front-batching). This round: vectorize ALL loads to
//     LDG.128 (~62 loads/thread), cutting LSU floor and instruction count ~3x.
//
// Inputs (metadata order): x(64,16), ry(16), rx(16), rz(16, unused), crz(16, unused),
//                          W(10,16), b(10). Output: float32 (64,10).

#define NW 16
#define BATCH 64
#define NOUT 10

__global__ __launch_bounds__(BATCH, 1)
void simpleqnn_kernel(const float* __restrict__ x,
                      const float* __restrict__ ry,
                      const float* __restrict__ rx,
                      const float* __restrict__ W,
                      const float* __restrict__ bias,
                      float* __restrict__ out) {
    const int b = threadIdx.x;   // blockDim.x == BATCH exactly

    // ---- vectorized loads: x row, ry, rx as float4 ----
    float xv[NW], ryv[NW], rxv[NW];
    {
        const float4* xrow = reinterpret_cast<const float4*>(x + b * NW);
        const float4* ry4  = reinterpret_cast<const float4*>(ry);
        const float4* rx4  = reinterpret_cast<const float4*>(rx);
#pragma unroll
        for (int i = 0; i < NW / 4; i++) {
            float4 a = xrow[i];
            float4 r = ry4[i];
            float4 c = rx4[i];
            xv[4*i+0] = a.x; xv[4*i+1] = a.y; xv[4*i+2] = a.z; xv[4*i+3] = a.w;
            ryv[4*i+0] = r.x; ryv[4*i+1] = r.y; ryv[4*i+2] = r.z; ryv[4*i+3] = r.w;
            rxv[4*i+0] = c.x; rxv[4*i+1] = c.y; rxv[4*i+2] = c.z; rxv[4*i+3] = c.w;
        }
    }

    // Per-wire Z expectation after RY(x), H, RY(ry), RX(rx) on |0>.
    // MUFU fast intrinsics: args are O(1), well inside the fast range.
    float z[NW];
#pragma unroll
    for (int v = 0; v < NW; v++) {
        z[v] = __cosf(rxv[v]) * __sinf(xv[v] - ryv[v]);
    }

    // Parity-mask expectations from the CNOT cascade
    float q[NW];
    float p = z[0];
#pragma unroll
    for (int w = 1; w < NW; w++) {
        p *= z[w];
        q[w] = p;
    }
    float s = z[1];
#pragma unroll
    for (int v = 2; v < NW; v++) s *= z[v];
    q[0] = s;

    // Final linear layer with float4 W loads: out[b,k] = sum_w q[w]*W[k,w] + bias[k]
#pragma unroll
    for (int k = 0; k < NOUT; k++) {
        const float4* wrow = reinterpret_cast<const float4*>(W + k * NW);
        float acc = bias[k];
#pragma unroll
        for (int i = 0; i < NW / 4; i++) {
            float4 wv = wrow[i];
            acc = fmaf(q[4*i+0], wv.x, acc);
            acc = fmaf(q[4*i+1], wv.y, acc);
            acc = fmaf(q[4*i+2], wv.z, acc);
            acc = fmaf(q[4*i+3], wv.w, acc);
        }
        out[b * NOUT + k] = acc;
    }
}

extern "C" void kernel_launch(void* const* d_in, const int* in_sizes, int n_in,
                              void* d_out, int out_size) {
    const float* x    = (const float*)d_in[0];   // (64,16)
    const float* ry   = (const float*)d_in[1];   // (16)
    const float* rx   = (const float*)d_in[2];   // (16)
    // d_in[3] = rz_params (unused: diagonal phases vanish in |psi|^2)
    // d_in[4] = crz_params (unused: same reason)
    const float* W    = (const float*)d_in[5];   // (10,16)
    const float* bias = (const float*)d_in[6];   // (10)
    float* out = (float*)d_out;                  // (64,10)

    simpleqnn_kernel<<<1, BATCH>>>(x, ry, rx, W, bias, out);
}

// round 9
// speedup vs baseline: 1.4381x; 1.0155x over previous
#include <cuda_runtime.h>

// SimpleQNN collapses analytically:
//   z[b,v]  = cos(rx[v]) * sin(x[b,v] - ry[v])
//   diagonal layers (CRZ, CZ, RZ) are pure phases -> no effect on probabilities
//   CNOT cascade -> parity masks: q_0 = prod_{1..15} z_v, q_w = prod_{0..w} z_v (w>=1)
//   out[b,k] = sum_w q[b,w] * W[k,w] + bias[k]
//
// Split z into per-batch sin part and uniform cos part:
//   q_w = S_w(b) * C_w,  S/C = same prefix masks over sin/cos factors.
//   C_w is batch-independent -> producer warp folds it into W once (smem):
//   W2[k,w] = W[k,w]*C_w;  out[b,k] = sum_w S_w(b)*W2[k,w] + bias[k].
//
// R6: libm sinf/cosf dominated (7.9us) -> MUFU intrinsics (5.2us).
// R7/R8: kernel is ~1600 cycles at idle DVFS clock; cost = MUFU rt + LDG issue
//        + register front-batching. This round: producer warp (threads 64..95)
//        computes cos/C/W2 in parallel with batch warps' sins; epilogue reads
//        W2 via broadcast LDS -> ~900 cycles expected.

#define NW 16
#define BATCH 64
#define NOUT 10
#define NTHREADS 96   // 2 batch warps + 1 producer warp

__global__ __launch_bounds__(NTHREADS, 1)
void simpleqnn_kernel(const float* __restrict__ x,
                      const float* __restrict__ ry,
                      const float* __restrict__ rx,
                      const float* __restrict__ W,
                      const float* __restrict__ bias,
                      float* __restrict__ out) {
    __shared__ float w2s[NOUT * NW];
    __shared__ float bs[NOUT];

    const int t = threadIdx.x;

    if (t >= BATCH) {
        // ---- producer warp: uniform cos prefixes folded into W ----
        const int lane = t - BATCH;  // 0..31
        float cv[NW];
        {
            const float4* rx4 = reinterpret_cast<const float4*>(rx);
#pragma unroll
            for (int i = 0; i < NW / 4; i++) {
                float4 c = rx4[i];
                cv[4*i+0] = __cosf(c.x); cv[4*i+1] = __cosf(c.y);
                cv[4*i+2] = __cosf(c.z); cv[4*i+3] = __cosf(c.w);
            }
        }
        float C[NW];
        float p = cv[0];
#pragma unroll
        for (int w = 1; w < NW; w++) { p *= cv[w]; C[w] = p; }
        float s0 = cv[1];
#pragma unroll
        for (int v = 2; v < NW; v++) s0 *= cv[v];
        C[0] = s0;

#pragma unroll
        for (int i = lane; i < NOUT * NW; i += 32)
            w2s[i] = W[i] * C[i & (NW - 1)];
        if (lane < NOUT) bs[lane] = bias[lane];

        __syncthreads();
        return;
    }

    // ---- batch warps: per-element sin parts (overlaps producer's cos work) ----
    float s[NW];
    {
        const float4* xrow = reinterpret_cast<const float4*>(x + t * NW);
        const float4* ry4  = reinterpret_cast<const float4*>(ry);
#pragma unroll
        for (int i = 0; i < NW / 4; i++) {
            float4 a = xrow[i];
            float4 r = ry4[i];
            s[4*i+0] = __sinf(a.x - r.x);
            s[4*i+1] = __sinf(a.y - r.y);
            s[4*i+2] = __sinf(a.z - r.z);
            s[4*i+3] = __sinf(a.w - r.w);
        }
    }

    // Prefix-product masks over sin factors
    float S[NW];
    float p = s[0];
#pragma unroll
    for (int w = 1; w < NW; w++) { p *= s[w]; S[w] = p; }
    float s0 = s[1];
#pragma unroll
    for (int v = 2; v < NW; v++) s0 *= s[v];
    S[0] = s0;

    __syncthreads();   // W2 + bias ready in smem

    // Epilogue: out[b,k] = sum_w S_w * W2[k,w] + bias[k]  (broadcast LDS.128)
#pragma unroll
    for (int k = 0; k < NOUT; k++) {
        const float4* wrow = reinterpret_cast<const float4*>(&w2s[k * NW]);
        float acc = bs[k];
#pragma unroll
        for (int i = 0; i < NW / 4; i++) {
            float4 wv = wrow[i];
            acc = fmaf(S[4*i+0], wv.x, acc);
            acc = fmaf(S[4*i+1], wv.y, acc);
            acc = fmaf(S[4*i+2], wv.z, acc);
            acc = fmaf(S[4*i+3], wv.w, acc);
        }
        out[t * NOUT + k] = acc;
    }
}

extern "C" void kernel_launch(void* const* d_in, const int* in_sizes, int n_in,
                              void* d_out, int out_size) {
    const float* x    = (const float*)d_in[0];   // (64,16)
    const float* ry   = (const float*)d_in[1];   // (16)
    const float* rx   = (const float*)d_in[2];   // (16)
    // d_in[3] = rz_params (unused: diagonal phases vanish in |psi|^2)
    // d_in[4] = crz_params (unused: same reason)
    const float* W    = (const float*)d_in[5];   // (10,16)
    const float* bias = (const float*)d_in[6];   // (10)
    float* out = (float*)d_out;                  // (64,10)

    simpleqnn_kernel<<<1, NTHREADS>>>(x, ry, rx, W, bias, out);
}